// round 1
// baseline (speedup 1.0000x reference)
#include <cuda_runtime.h>
#include <math.h>

#define D 128
#define PAD 132            // 128 + 4 floats: breaks worst smem bank patterns, keeps 16B alignment
#define NMAX 65536

static __device__ int   g_degi[NMAX];
static __device__ float g_dinv[NMAX];
static __device__ float g_p[NMAX];
static __device__ float g_sacc[NMAX];
static __device__ float g_scores[NMAX];
static __device__ __align__(16) float g_G[D * D];
static __device__ float g_v1[D];
static __device__ float g_a1[D];
static __device__ float g_wv[D];
static __device__ float g_bg;
static __device__ int   g_i32;   // 1 => edge_index is int32, 0 => int64

// ---------------------------------------------------------------- utilities
__device__ __forceinline__ void load_edge(const void* ei, int E, int e, int& s, int& t) {
    if (g_i32) {
        const int* p = (const int*)ei;
        s = p[e]; t = p[E + e];
    } else {
        const long long* p = (const long long*)ei;
        s = (int)p[e]; t = (int)p[E + e];
    }
}

__device__ __forceinline__ float sigmoidf_(float z) {
    return 1.0f / (1.0f + expf(-z));
}

// ---------------------------------------------------------------- small kernels
__global__ void k_zero(int N) {
    int i = blockIdx.x * 256 + threadIdx.x;
    if (i < N) g_degi[i] = 0;
    if (i < D * D) g_G[i] = 0.0f;
    if (i == 0) g_i32 = 0;
}

// Detect edge_index dtype: if the buffer is really int32, int64-reads combine
// adjacent values -> huge numbers >= N (P(miss) ~ (1/N)^1024 ~ 0).
__global__ void k_detect(const long long* ei, int E, int N) {
    int e = blockIdx.x * 256 + threadIdx.x;
    int n = E < 1024 ? E : 1024;
    if (e < n) {
        unsigned long long v = (unsigned long long)ei[e];
        if (v >= (unsigned long long)N) g_i32 = 1;
    }
}

// wv = w_gcn @ w_score ; bg = b_gcn . w_score + b_score
__global__ void k_setup(const float* __restrict__ wg, const float* __restrict__ bgc,
                        const float* __restrict__ ws, const float* __restrict__ bs) {
    __shared__ float wss[D];
    int t = threadIdx.x;
    wss[t] = ws[t];
    __syncthreads();
    float s = 0.0f;
    #pragma unroll 8
    for (int m = 0; m < D; m++) s += wg[t * D + m] * wss[m];
    g_wv[t] = s;
    if (t == 0) {
        float b = bs[0];
        for (int m = 0; m < D; m++) b += bgc[m] * wss[m];
        g_bg = b;
    }
}

__global__ void k_deg(const void* ei, int E) {
    int e = blockIdx.x * 256 + threadIdx.x;
    if (e >= E) return;
    int s, t; load_edge(ei, E, e, s, t);
    (void)s;
    atomicAdd(&g_degi[t], 1);
}

__global__ void k_dinv(int N) {
    int i = blockIdx.x * 256 + threadIdx.x;
    if (i >= N) return;
    float di = rsqrtf((float)(g_degi[i] + 1));   // +1 = self loop, deg always > 0
    g_dinv[i] = di;
    g_sacc[i] = di * di * g_p[i];                // self-loop contribution
}

__global__ void k_edge(const void* ei, int E) {
    int e = blockIdx.x * 256 + threadIdx.x;
    if (e >= E) return;
    int s, t; load_edge(ei, E, e, s, t);
    atomicAdd(&g_sacc[t], g_dinv[s] * g_dinv[t] * g_p[s]);
}

__global__ void k_scores(int N) {
    int i = blockIdx.x * 256 + threadIdx.x;
    if (i >= N) return;
    g_scores[i] = sigmoidf_(g_sacc[i] + g_bg);
}

__global__ void k_gate(const void* ei, const float* __restrict__ ew,
                       const float* __restrict__ al, const float* __restrict__ be,
                       float* __restrict__ out, int E) {
    int e = blockIdx.x * 256 + threadIdx.x;
    if (e >= E) return;
    int s, t; load_edge(ei, E, e, s, t);
    float z = al[0] * (g_scores[s] + g_scores[t]) + be[0];
    out[e] = ew[e] * sigmoidf_(z);
}

// ---------------------------------------------------------------- Gram + p
// Persistent: each block accumulates its 128x128 Gram partial in registers
// across its row-chunks, atomics once at the end. Also computes p = x @ wv.
__global__ void k_G_p(const float* __restrict__ x, int N, int nChunks) {
    extern __shared__ float xs[];         // 128 * PAD floats (row-major x chunk)
    __shared__ float wv_s[D];
    int tid = threadIdx.x;
    int ty = tid >> 4, tx = tid & 15;
    int r0 = ty * 8, c0 = tx * 8;
    if (tid < D) wv_s[tid] = g_wv[tid];

    float acc[8][8];
    #pragma unroll
    for (int i = 0; i < 8; i++)
        #pragma unroll
        for (int j = 0; j < 8; j++) acc[i][j] = 0.0f;

    for (int ch = blockIdx.x; ch < nChunks; ch += gridDim.x) {
        int R0 = ch * 128;
        __syncthreads();
        for (int idx = tid; idx < 128 * 32; idx += 256) {
            int r = idx >> 5, c4 = idx & 31;
            int gr = R0 + r;
            float4 v = (gr < N) ? ((const float4*)x)[(size_t)gr * 32 + c4]
                                : make_float4(0.f, 0.f, 0.f, 0.f);
            *(float4*)&xs[r * PAD + c4 * 4] = v;
        }
        __syncthreads();
        if (tid < 128) {
            int gr = R0 + tid;
            if (gr < N) {
                float s = 0.0f;
                #pragma unroll 8
                for (int d = 0; d < D; d++) s += xs[tid * PAD + d] * wv_s[d];
                g_p[gr] = s;
            }
        }
        #pragma unroll 4
        for (int k = 0; k < 128; k++) {
            float a[8], b[8];
            *(float4*)&a[0] = *(const float4*)&xs[k * PAD + r0];
            *(float4*)&a[4] = *(const float4*)&xs[k * PAD + r0 + 4];
            *(float4*)&b[0] = *(const float4*)&xs[k * PAD + c0];
            *(float4*)&b[4] = *(const float4*)&xs[k * PAD + c0 + 4];
            #pragma unroll
            for (int i = 0; i < 8; i++)
                #pragma unroll
                for (int j = 0; j < 8; j++) acc[i][j] += a[i] * b[j];
        }
    }
    #pragma unroll
    for (int i = 0; i < 8; i++)
        #pragma unroll
        for (int j = 0; j < 8; j++)
            atomicAdd(&g_G[(r0 + i) * D + (c0 + j)], acc[i][j]);
}

// ---------------------------------------------------------------- top eigenvector
// Repeated normalized squaring of symmetric G in shared memory (exponent 2^12),
// then extract dominant column + 3 refinement matvecs. Only v1 is needed (k==1
// always: SVD singular values are descending so diff(S) <= 0 < 0.1).
__global__ void k_eigen(const float* __restrict__ w1) {
    extern __shared__ float sm[];
    float* As  = sm;                    // 128*PAD
    float* vv  = sm + 128 * PAD;        // 128
    float* uu  = vv + 128;              // 128
    float* red = uu + 128;              // 256
    __shared__ int jm;
    int tid = threadIdx.x;
    int ty = tid >> 4, tx = tid & 15;
    int r0 = ty * 8, c0 = tx * 8;

    for (int idx = tid; idx < D * 32; idx += 256) {
        int r = idx >> 5, c4 = idx & 31;
        *(float4*)&As[r * PAD + c4 * 4] = ((const float4*)g_G)[idx];
    }
    __syncthreads();

    for (int it = 0; it < 12; it++) {
        float acc[8][8];
        #pragma unroll
        for (int i = 0; i < 8; i++)
            #pragma unroll
            for (int j = 0; j < 8; j++) acc[i][j] = 0.0f;
        // B = A*A using symmetry: B[r][c] = sum_k A[k][r]*A[k][c] (row-k reads)
        #pragma unroll 4
        for (int k = 0; k < D; k++) {
            float a[8], b[8];
            *(float4*)&a[0] = *(const float4*)&As[k * PAD + r0];
            *(float4*)&a[4] = *(const float4*)&As[k * PAD + r0 + 4];
            *(float4*)&b[0] = *(const float4*)&As[k * PAD + c0];
            *(float4*)&b[4] = *(const float4*)&As[k * PAD + c0 + 4];
            #pragma unroll
            for (int i = 0; i < 8; i++)
                #pragma unroll
                for (int j = 0; j < 8; j++) acc[i][j] += a[i] * b[j];
        }
        float m = 0.0f;
        #pragma unroll
        for (int i = 0; i < 8; i++)
            #pragma unroll
            for (int j = 0; j < 8; j++) m = fmaxf(m, fabsf(acc[i][j]));
        red[tid] = m;
        __syncthreads();
        for (int s = 128; s > 0; s >>= 1) {
            if (tid < s) red[tid] = fmaxf(red[tid], red[tid + s]);
            __syncthreads();
        }
        float scale = red[0] > 0.0f ? 1.0f / red[0] : 1.0f;
        #pragma unroll
        for (int i = 0; i < 8; i++)
            #pragma unroll
            for (int j = 0; j < 8; j++)
                As[(r0 + i) * PAD + (c0 + j)] = acc[i][j] * scale;
        __syncthreads();
    }

    if (tid == 0) {
        float best = -1e30f; int bj = 0;
        for (int j = 0; j < D; j++) {
            float d = As[j * PAD + j];
            if (d > best) { best = d; bj = j; }
        }
        jm = bj;
    }
    __syncthreads();
    if (tid < D) vv[tid] = As[jm * PAD + tid];
    __syncthreads();

    for (int t = 0; t < 3; t++) {
        if (tid < D) {
            float s = 0.0f;
            #pragma unroll 8
            for (int c = 0; c < D; c++) s += As[tid * PAD + c] * vv[c];
            uu[tid] = s;
        }
        __syncthreads();
        red[tid] = (tid < D) ? uu[tid] * uu[tid] : 0.0f;
        __syncthreads();
        for (int s = 128; s > 0; s >>= 1) {
            if (tid < s) red[tid] += red[tid + s];
            __syncthreads();
        }
        float inv = rsqrtf(fmaxf(red[0], 1e-30f));
        __syncthreads();
        if (tid < D) vv[tid] = uu[tid] * inv;
        __syncthreads();
    }

    if (tid < D) {
        g_v1[tid] = vv[tid];
        float s = 0.0f;
        #pragma unroll 8
        for (int d = 0; d < D; d++) s += vv[d] * w1[d * D + tid];   // a1 = w_e1^T v1
        g_a1[tid] = s;
    }
}

// ---------------------------------------------------------------- fused enhancer
// out = (relu(0.5 x@W1 + 0.5 q a1^T + b1) @ W2 + b2)*scores + 0.5 x + 0.5 q v1^T
// Both weight matrices stay resident in shared; x read twice (GEMM + residual).
__global__ void k_final(const float* __restrict__ x,
                        const float* __restrict__ b1, const float* __restrict__ b2,
                        const float* __restrict__ w1, const float* __restrict__ w2,
                        float* __restrict__ out, int N, int nChunks) {
    extern __shared__ float sm[];
    float* bufA = sm;                      // 128*PAD : x^T chunk, then relu(z)^T
    float* w1s  = sm + 128 * PAD;          // 128*PAD
    float* w2s  = w1s + 128 * PAD;         // 128*PAD
    float* q_s  = w2s + 128 * PAD;         // 128
    float* sc_s = q_s + 128;               // 128
    __shared__ float v1_s[D], a1_s[D], be1_s[D], be2_s[D];

    int tid = threadIdx.x;
    int ty = tid >> 4, tx = tid & 15;
    int r0 = ty * 8, c0 = tx * 8;

    for (int idx = tid; idx < D * 32; idx += 256) {
        int r = idx >> 5, c4 = idx & 31;
        *(float4*)&w1s[r * PAD + c4 * 4] = ((const float4*)w1)[idx];
        *(float4*)&w2s[r * PAD + c4 * 4] = ((const float4*)w2)[idx];
    }
    if (tid < D) {
        v1_s[tid] = g_v1[tid]; a1_s[tid] = g_a1[tid];
        be1_s[tid] = b1[tid];  be2_s[tid] = b2[tid];
    }

    for (int ch = blockIdx.x; ch < nChunks; ch += gridDim.x) {
        int R0 = ch * 128;
        __syncthreads();
        // load x chunk transposed: bufA[d][r] = x[R0+r][d]
        for (int idx = tid; idx < 128 * 32; idx += 256) {
            int r = idx >> 5, c4 = idx & 31;
            int gr = R0 + r;
            float4 v = (gr < N) ? ((const float4*)x)[(size_t)gr * 32 + c4]
                                : make_float4(0.f, 0.f, 0.f, 0.f);
            int cb = c4 * 4;
            bufA[(cb + 0) * PAD + r] = v.x;
            bufA[(cb + 1) * PAD + r] = v.y;
            bufA[(cb + 2) * PAD + r] = v.z;
            bufA[(cb + 3) * PAD + r] = v.w;
        }
        if (tid < 128) sc_s[tid] = (R0 + tid < N) ? g_scores[R0 + tid] : 0.0f;
        __syncthreads();
        if (tid < 128) {
            float q = 0.0f;
            #pragma unroll 8
            for (int d = 0; d < D; d++) q += bufA[d * PAD + tid] * v1_s[d];
            q_s[tid] = q;
        }
        __syncthreads();

        // GEMM1: z = x @ W1
        float acc[8][8];
        #pragma unroll
        for (int i = 0; i < 8; i++)
            #pragma unroll
            for (int j = 0; j < 8; j++) acc[i][j] = 0.0f;
        #pragma unroll 4
        for (int k = 0; k < D; k++) {
            float a[8], b[8];
            *(float4*)&a[0] = *(const float4*)&bufA[k * PAD + r0];
            *(float4*)&a[4] = *(const float4*)&bufA[k * PAD + r0 + 4];
            *(float4*)&b[0] = *(const float4*)&w1s[k * PAD + c0];
            *(float4*)&b[4] = *(const float4*)&w1s[k * PAD + c0 + 4];
            #pragma unroll
            for (int i = 0; i < 8; i++)
                #pragma unroll
                for (int j = 0; j < 8; j++) acc[i][j] += a[i] * b[j];
        }
        // epilogue 1: fold x_fused + bias, relu
        #pragma unroll
        for (int i = 0; i < 8; i++) {
            float q = q_s[r0 + i];
            #pragma unroll
            for (int j = 0; j < 8; j++) {
                float z = 0.5f * acc[i][j] + 0.5f * q * a1_s[c0 + j] + be1_s[c0 + j];
                acc[i][j] = z > 0.0f ? z : 0.0f;
            }
        }
        __syncthreads();            // all GEMM1 reads of bufA complete
        #pragma unroll
        for (int i = 0; i < 8; i++)
            #pragma unroll
            for (int j = 0; j < 8; j++)
                bufA[(c0 + j) * PAD + (r0 + i)] = acc[i][j];   // relu(z)^T
        __syncthreads();

        // GEMM2: enh = relu(z) @ W2
        float acc2[8][8];
        #pragma unroll
        for (int i = 0; i < 8; i++)
            #pragma unroll
            for (int j = 0; j < 8; j++) acc2[i][j] = 0.0f;
        #pragma unroll 4
        for (int k = 0; k < D; k++) {
            float a[8], b[8];
            *(float4*)&a[0] = *(const float4*)&bufA[k * PAD + r0];
            *(float4*)&a[4] = *(const float4*)&bufA[k * PAD + r0 + 4];
            *(float4*)&b[0] = *(const float4*)&w2s[k * PAD + c0];
            *(float4*)&b[4] = *(const float4*)&w2s[k * PAD + c0 + 4];
            #pragma unroll
            for (int i = 0; i < 8; i++)
                #pragma unroll
                for (int j = 0; j < 8; j++) acc2[i][j] += a[i] * b[j];
        }
        // epilogue 2: residual + write
        #pragma unroll
        for (int i = 0; i < 8; i++) {
            int gr = R0 + r0 + i;
            if (gr >= N) continue;
            float sc = sc_s[r0 + i], q = q_s[r0 + i];
            float xv[8];
            *(float4*)&xv[0] = ((const float4*)x)[(size_t)gr * 32 + (c0 >> 2)];
            *(float4*)&xv[4] = ((const float4*)x)[(size_t)gr * 32 + (c0 >> 2) + 1];
            float o[8];
            #pragma unroll
            for (int j = 0; j < 8; j++)
                o[j] = (acc2[i][j] + be2_s[c0 + j]) * sc
                     + 0.5f * xv[j] + 0.5f * q * v1_s[c0 + j];
            ((float4*)out)[(size_t)gr * 32 + (c0 >> 2)]     = *(float4*)&o[0];
            ((float4*)out)[(size_t)gr * 32 + (c0 >> 2) + 1] = *(float4*)&o[4];
        }
    }
}

// ---------------------------------------------------------------- launch
extern "C" void kernel_launch(void* const* d_in, const int* in_sizes, int n_in,
                              void* d_out, int out_size) {
    const float* x       = (const float*)d_in[0];
    const void*  ei      = d_in[1];
    const float* ew      = (const float*)d_in[2];
    const float* w_gcn   = (const float*)d_in[3];
    const float* b_gcn   = (const float*)d_in[4];
    const float* w_score = (const float*)d_in[5];
    const float* b_score = (const float*)d_in[6];
    const float* alpha   = (const float*)d_in[7];
    const float* beta    = (const float*)d_in[8];
    const float* w_e1    = (const float*)d_in[9];
    const float* b_e1    = (const float*)d_in[10];
    const float* w_e2    = (const float*)d_in[11];
    const float* b_e2    = (const float*)d_in[12];
    float* out = (float*)d_out;

    int N = in_sizes[0] / D;
    int E = in_sizes[2];
    int nChunks = (N + 127) / 128;
    int NB = (N + 255) / 256;
    int EB = (E + 255) / 256;
    int ZB = ((N > D * D ? N : D * D) + 255) / 256;

    static int attr_done = 0;
    if (!attr_done) {
        cudaFuncSetAttribute(k_G_p,   cudaFuncAttributeMaxDynamicSharedMemorySize, 128 * PAD * 4);
        cudaFuncSetAttribute(k_eigen, cudaFuncAttributeMaxDynamicSharedMemorySize, (128 * PAD + 512) * 4);
        cudaFuncSetAttribute(k_final, cudaFuncAttributeMaxDynamicSharedMemorySize, (3 * 128 * PAD + 256) * 4);
        attr_done = 1;
    }

    k_zero<<<ZB, 256>>>(N);
    k_detect<<<4, 256>>>((const long long*)ei, E, N);
    k_setup<<<1, 128>>>(w_gcn, b_gcn, w_score, b_score);
    k_G_p<<<148, 256, 128 * PAD * 4>>>(x, N, nChunks);
    k_deg<<<EB, 256>>>(ei, E);
    k_dinv<<<NB, 256>>>(N);
    k_edge<<<EB, 256>>>(ei, E);
    k_scores<<<NB, 256>>>(N);
    k_gate<<<EB, 256>>>(ei, ew, alpha, beta, out + (size_t)N * D, E);
    k_eigen<<<1, 256, (128 * PAD + 512) * 4>>>(w_e1);
    k_final<<<148, 256, (3 * 128 * PAD + 256) * 4>>>(x, b_e1, b_e2, w_e1, w_e2, out, N, nChunks);
}

// round 2
// speedup vs baseline: 1.2450x; 1.2450x over previous
#include <cuda_runtime.h>
#include <math.h>

#define D 128
#define PAD 132            // bufA/weight row pitch (floats)
#define PADE 129           // eigen-extract pitch: (t+c) mod 32 -> conflict-free column walks
#define NMAX 65536

static __device__ int   g_degi[NMAX];
static __device__ float g_dinv[NMAX];
static __device__ float g_p[NMAX];
static __device__ float g_sacc[NMAX];
static __device__ float g_scores[NMAX];
static __device__ __align__(16) float g_G[D * D];
static __device__ __align__(16) float g_Ea[D * D];
static __device__ __align__(16) float g_Eb[D * D];
static __device__ float g_scale[16];
static __device__ float g_v1[D];
static __device__ float g_a1[D];
static __device__ float g_wv[D];
static __device__ float g_bg;
static __device__ int   g_i32;   // 1 => edge_index is int32, 0 => int64

// ---------------------------------------------------------------- utilities
__device__ __forceinline__ void load_edge(const void* ei, int E, int e, int& s, int& t) {
    if (g_i32) {
        const int* p = (const int*)ei;
        s = p[e]; t = p[E + e];
    } else {
        const long long* p = (const long long*)ei;
        s = (int)p[e]; t = (int)p[E + e];
    }
}

__device__ __forceinline__ float sigmoidf_(float z) {
    return 1.0f / (1.0f + expf(-z));
}

// ---------------------------------------------------------------- small kernels
__global__ void k_zero(int N) {
    int i = blockIdx.x * 256 + threadIdx.x;
    if (i < N) g_degi[i] = 0;
    if (i < D * D) g_G[i] = 0.0f;
    if (i < 16) g_scale[i] = 0.0f;
    if (i == 16) g_i32 = 0;
}

// Detect edge_index dtype: int32 data read as int64 combines adjacent indices -> >= N.
__global__ void k_detect(const long long* ei, int E, int N) {
    int e = blockIdx.x * 256 + threadIdx.x;
    int n = E < 1024 ? E : 1024;
    if (e < n) {
        unsigned long long v = (unsigned long long)ei[e];
        if (v >= (unsigned long long)N) g_i32 = 1;
    }
}

// wv = w_gcn @ w_score ; bg = b_gcn . w_score + b_score
__global__ void k_setup(const float* __restrict__ wg, const float* __restrict__ bgc,
                        const float* __restrict__ ws, const float* __restrict__ bs) {
    __shared__ float wss[D];
    int t = threadIdx.x;
    wss[t] = ws[t];
    __syncthreads();
    float s = 0.0f;
    #pragma unroll 8
    for (int m = 0; m < D; m++) s += wg[t * D + m] * wss[m];
    g_wv[t] = s;
    if (t == 0) {
        float b = bs[0];
        for (int m = 0; m < D; m++) b += bgc[m] * wss[m];
        g_bg = b;
    }
}

// p = x @ wv : one warp per row, coalesced float4 per lane
__global__ void k_p(const float* __restrict__ x, int N) {
    int w = (blockIdx.x * blockDim.x + threadIdx.x) >> 5;
    int lane = threadIdx.x & 31;
    if (w >= N) return;
    float4 xv = ((const float4*)x)[(size_t)w * 32 + lane];
    float4 wv = *(const float4*)&g_wv[lane * 4];
    float s = xv.x * wv.x + xv.y * wv.y + xv.z * wv.z + xv.w * wv.w;
    #pragma unroll
    for (int o = 16; o; o >>= 1) s += __shfl_xor_sync(0xffffffffu, s, o);
    if (lane == 0) g_p[w] = s;
}

__global__ void k_deg(const void* ei, int E) {
    int e = blockIdx.x * 256 + threadIdx.x;
    if (e >= E) return;
    int s, t; load_edge(ei, E, e, s, t);
    (void)s;
    atomicAdd(&g_degi[t], 1);
}

__global__ void k_dinv(int N) {
    int i = blockIdx.x * 256 + threadIdx.x;
    if (i >= N) return;
    float di = rsqrtf((float)(g_degi[i] + 1));   // +1 = self loop
    g_dinv[i] = di;
    g_sacc[i] = di * di * g_p[i];                // self-loop contribution
}

__global__ void k_edge(const void* ei, int E) {
    int e = blockIdx.x * 256 + threadIdx.x;
    if (e >= E) return;
    int s, t; load_edge(ei, E, e, s, t);
    atomicAdd(&g_sacc[t], g_dinv[s] * g_dinv[t] * g_p[s]);
}

__global__ void k_scores(int N) {
    int i = blockIdx.x * 256 + threadIdx.x;
    if (i >= N) return;
    g_scores[i] = sigmoidf_(g_sacc[i] + g_bg);
}

__global__ void k_gate(const void* ei, const float* __restrict__ ew,
                       const float* __restrict__ al, const float* __restrict__ be,
                       float* __restrict__ out, int E) {
    int e = blockIdx.x * 256 + threadIdx.x;
    if (e >= E) return;
    int s, t; load_edge(ei, E, e, s, t);
    float z = al[0] * (g_scores[s] + g_scores[t]) + be[0];
    out[e] = ew[e] * sigmoidf_(z);
}

// ---------------------------------------------------------------- Gram
// 512 threads, 4x8 tiles, split columns {tx*4, tx*4+64} -> all b LDS.128 conflict-free.
__global__ __launch_bounds__(512, 2) void k_G(const float* __restrict__ x, int N, int nChunks) {
    extern __shared__ float xs[];         // 128 * PAD
    int tid = threadIdx.x;
    int ty = tid >> 4, tx = tid & 15;
    int r0 = ty * 4, cA = tx * 4, cB = cA + 64;

    float acc[4][8];
    #pragma unroll
    for (int i = 0; i < 4; i++)
        #pragma unroll
        for (int j = 0; j < 8; j++) acc[i][j] = 0.0f;

    for (int ch = blockIdx.x; ch < nChunks; ch += gridDim.x) {
        int R0 = ch * 128;
        __syncthreads();
        for (int idx = tid; idx < 128 * 32; idx += 512) {
            int r = idx >> 5, c4 = idx & 31;
            int gr = R0 + r;
            float4 v = (gr < N) ? ((const float4*)x)[(size_t)gr * 32 + c4]
                                : make_float4(0.f, 0.f, 0.f, 0.f);
            *(float4*)&xs[r * PAD + c4 * 4] = v;
        }
        __syncthreads();
        #pragma unroll 4
        for (int k = 0; k < 128; k++) {
            float4 av = *(const float4*)&xs[k * PAD + r0];
            float4 b0 = *(const float4*)&xs[k * PAD + cA];
            float4 b1 = *(const float4*)&xs[k * PAD + cB];
            float a[4] = {av.x, av.y, av.z, av.w};
            float b[8] = {b0.x, b0.y, b0.z, b0.w, b1.x, b1.y, b1.z, b1.w};
            #pragma unroll
            for (int i = 0; i < 4; i++)
                #pragma unroll
                for (int j = 0; j < 8; j++) acc[i][j] += a[i] * b[j];
        }
    }
    #pragma unroll
    for (int i = 0; i < 4; i++) {
        #pragma unroll
        for (int j = 0; j < 4; j++) {
            atomicAdd(&g_G[(r0 + i) * D + cA + j], acc[i][j]);
            atomicAdd(&g_G[(r0 + i) * D + cB + j], acc[i][j + 4]);
        }
    }
}

__global__ void k_gmax() {
    __shared__ float red[256];
    int t = threadIdx.x;
    float m = 0.0f;
    for (int i = t; i < D * D; i += 256) m = fmaxf(m, fabsf(g_G[i]));
    red[t] = m;
    __syncthreads();
    for (int s = 128; s > 0; s >>= 1) {
        if (t < s) red[t] = fmaxf(red[t], red[t + s]);
        __syncthreads();
    }
    if (t == 0) g_scale[0] = red[0];
}

// ---------------------------------------------------------------- matrix squaring (multi-SM)
// B = (A/s) * (A/s); raw write + atomicMax(|B|) into next scale. 8 blocks x 256 threads.
__global__ void k_sq(int it) {
    extern __shared__ float As[];   // 128*128
    const float* in = (it == 0) ? g_G : ((it & 1) ? g_Ea : g_Eb);
    float* outp = (it & 1) ? g_Eb : g_Ea;
    float inv = 1.0f / g_scale[it];
    int tid = threadIdx.x;
    for (int idx = tid; idx < D * D / 4; idx += 256) {
        float4 v = ((const float4*)in)[idx];
        v.x *= inv; v.y *= inv; v.z *= inv; v.w *= inv;
        ((float4*)As)[idx] = v;
    }
    __syncthreads();
    int ty = tid >> 5, tx = tid & 31;
    int r0 = blockIdx.x * 16 + ty * 2, c0 = tx * 4;
    float acc0[4] = {0.f, 0.f, 0.f, 0.f};
    float acc1[4] = {0.f, 0.f, 0.f, 0.f};
    #pragma unroll 4
    for (int k = 0; k < D; k++) {
        float a0 = As[r0 * D + k];
        float a1v = As[(r0 + 1) * D + k];
        float4 b = *(const float4*)&As[k * D + c0];
        acc0[0] += a0 * b.x; acc0[1] += a0 * b.y; acc0[2] += a0 * b.z; acc0[3] += a0 * b.w;
        acc1[0] += a1v * b.x; acc1[1] += a1v * b.y; acc1[2] += a1v * b.z; acc1[3] += a1v * b.w;
    }
    *(float4*)&outp[r0 * D + c0] = *(float4*)&acc0[0];
    *(float4*)&outp[(r0 + 1) * D + c0] = *(float4*)&acc1[0];
    float m = 0.0f;
    #pragma unroll
    for (int j = 0; j < 4; j++) m = fmaxf(m, fmaxf(fabsf(acc0[j]), fabsf(acc1[j])));
    #pragma unroll
    for (int o = 16; o; o >>= 1) m = fmaxf(m, __shfl_xor_sync(0xffffffffu, m, o));
    if (tx == 0) atomicMax((int*)&g_scale[it + 1], __float_as_int(m));  // all values positive
}

// ---------------------------------------------------------------- v1 extraction + a1
__global__ void k_extract(const float* __restrict__ w1) {
    extern __shared__ float sm[];
    float* As = sm;                  // 128*PADE
    float* vv = sm + D * PADE;       // 128
    float* uu = vv + D;              // 128
    float* red = uu + D;             // 128
    __shared__ int redi[128];
    __shared__ int jm;
    int t = threadIdx.x;             // 128 threads

    for (int idx = t; idx < D * D; idx += 128) {
        int r = idx >> 7, c = idx & 127;
        As[r * PADE + c] = g_Eb[idx];
    }
    __syncthreads();
    red[t] = As[t * PADE + t]; redi[t] = t;
    __syncthreads();
    for (int s = 64; s > 0; s >>= 1) {
        if (t < s && red[t + s] > red[t]) { red[t] = red[t + s]; redi[t] = redi[t + s]; }
        __syncthreads();
    }
    if (t == 0) jm = redi[0];
    __syncthreads();
    vv[t] = As[jm * PADE + t];
    __syncthreads();

    for (int itr = 0; itr < 3; itr++) {
        float s = 0.0f;
        #pragma unroll 8
        for (int c = 0; c < D; c++) s += As[t * PADE + c] * vv[c];
        uu[t] = s;
        red[t] = s * s;
        __syncthreads();
        for (int r2 = 64; r2 > 0; r2 >>= 1) {
            if (t < r2) red[t] += red[t + r2];
            __syncthreads();
        }
        float inv = rsqrtf(fmaxf(red[0], 1e-30f));
        __syncthreads();
        vv[t] = uu[t] * inv;
        __syncthreads();
    }

    g_v1[t] = vv[t];
    float a = 0.0f;
    #pragma unroll 8
    for (int d2 = 0; d2 < D; d2++) a += vv[d2] * w1[d2 * D + t];
    g_a1[t] = a;
}

// ---------------------------------------------------------------- fused enhancer
// out = (relu(0.5 x@W1 + 0.5 q a1^T + b1) @ W2 + b2)*scores + 0.5 x + 0.5 q v1^T
// x kept row-major in smem (no transpose), residual x-tile kept in registers -> x read ONCE.
__global__ __launch_bounds__(512, 1) void k_final(const float* __restrict__ x,
                        const float* __restrict__ b1, const float* __restrict__ b2,
                        const float* __restrict__ w1, const float* __restrict__ w2,
                        float* __restrict__ out, int N, int nChunks) {
    extern __shared__ float sm[];
    float* xs  = sm;                       // 128*PAD : x chunk, later relu(z)
    float* w1s = sm + 128 * PAD;
    float* w2s = w1s + 128 * PAD;
    float* q_s = w2s + 128 * PAD;          // 128
    float* sc_s = q_s + 128;               // 128
    __shared__ float v1_s[D], a1_s[D], be1_s[D], be2_s[D];

    int tid = threadIdx.x;
    int ty = tid >> 4, tx = tid & 15;
    int r0 = ty * 4, cA = tx * 4, cB = cA + 64;

    for (int idx = tid; idx < D * 32; idx += 512) {
        int r = idx >> 5, c4 = idx & 31;
        *(float4*)&w1s[r * PAD + c4 * 4] = ((const float4*)w1)[idx];
        *(float4*)&w2s[r * PAD + c4 * 4] = ((const float4*)w2)[idx];
    }
    if (tid < D) {
        v1_s[tid] = g_v1[tid]; a1_s[tid] = g_a1[tid];
        be1_s[tid] = b1[tid];  be2_s[tid] = b2[tid];
    }

    for (int ch = blockIdx.x; ch < nChunks; ch += gridDim.x) {
        int R0 = ch * 128;
        __syncthreads();
        for (int idx = tid; idx < 128 * 32; idx += 512) {
            int r = idx >> 5, c4 = idx & 31;
            int gr = R0 + r;
            float4 v = (gr < N) ? ((const float4*)x)[(size_t)gr * 32 + c4]
                                : make_float4(0.f, 0.f, 0.f, 0.f);
            *(float4*)&xs[r * PAD + c4 * 4] = v;
        }
        if (tid < 128) sc_s[tid] = (R0 + tid < N) ? g_scores[R0 + tid] : 0.0f;
        __syncthreads();
        if (tid < 128) {
            float q = 0.0f;
            #pragma unroll 8
            for (int d = 0; d < D; d++) q += xs[tid * PAD + d] * v1_s[d];
            q_s[tid] = q;
        }
        // keep residual x-tile in registers (xs will be overwritten by relu(z))
        float xv[4][8];
        #pragma unroll
        for (int i = 0; i < 4; i++) {
            *(float4*)&xv[i][0] = *(const float4*)&xs[(r0 + i) * PAD + cA];
            *(float4*)&xv[i][4] = *(const float4*)&xs[(r0 + i) * PAD + cB];
        }
        __syncthreads();   // q_s visible

        // GEMM1: z = x @ W1 (scalar broadcast a-loads, conflict-free b-loads)
        float acc[4][8];
        #pragma unroll
        for (int i = 0; i < 4; i++)
            #pragma unroll
            for (int j = 0; j < 8; j++) acc[i][j] = 0.0f;
        #pragma unroll 4
        for (int k = 0; k < 128; k++) {
            float a[4];
            #pragma unroll
            for (int i = 0; i < 4; i++) a[i] = xs[(r0 + i) * PAD + k];
            float4 b0 = *(const float4*)&w1s[k * PAD + cA];
            float4 b1v = *(const float4*)&w1s[k * PAD + cB];
            float b[8] = {b0.x, b0.y, b0.z, b0.w, b1v.x, b1v.y, b1v.z, b1v.w};
            #pragma unroll
            for (int i = 0; i < 4; i++)
                #pragma unroll
                for (int j = 0; j < 8; j++) acc[i][j] += a[i] * b[j];
        }
        // epilogue 1: fold x_fused + bias, relu
        #pragma unroll
        for (int i = 0; i < 4; i++) {
            float q = q_s[r0 + i];
            #pragma unroll
            for (int j = 0; j < 8; j++) {
                int col = (j < 4) ? (cA + j) : (cB + j - 4);
                float z = 0.5f * acc[i][j] + 0.5f * q * a1_s[col] + be1_s[col];
                acc[i][j] = z > 0.0f ? z : 0.0f;
            }
        }
        __syncthreads();            // all GEMM1 reads of xs complete
        #pragma unroll
        for (int i = 0; i < 4; i++) {
            *(float4*)&xs[(r0 + i) * PAD + cA] = *(float4*)&acc[i][0];
            *(float4*)&xs[(r0 + i) * PAD + cB] = *(float4*)&acc[i][4];
        }
        __syncthreads();

        // GEMM2: enh = relu(z) @ W2
        #pragma unroll
        for (int i = 0; i < 4; i++)
            #pragma unroll
            for (int j = 0; j < 8; j++) acc[i][j] = 0.0f;
        #pragma unroll 4
        for (int k = 0; k < 128; k++) {
            float a[4];
            #pragma unroll
            for (int i = 0; i < 4; i++) a[i] = xs[(r0 + i) * PAD + k];
            float4 b0 = *(const float4*)&w2s[k * PAD + cA];
            float4 b1v = *(const float4*)&w2s[k * PAD + cB];
            float b[8] = {b0.x, b0.y, b0.z, b0.w, b1v.x, b1v.y, b1v.z, b1v.w};
            #pragma unroll
            for (int i = 0; i < 4; i++)
                #pragma unroll
                for (int j = 0; j < 8; j++) acc[i][j] += a[i] * b[j];
        }
        // epilogue 2: residual + write
        #pragma unroll
        for (int i = 0; i < 4; i++) {
            int gr = R0 + r0 + i;
            if (gr >= N) continue;
            float sc = sc_s[r0 + i], q = q_s[r0 + i];
            float o[8];
            #pragma unroll
            for (int j = 0; j < 8; j++) {
                int col = (j < 4) ? (cA + j) : (cB + j - 4);
                o[j] = (acc[i][j] + be2_s[col]) * sc
                     + 0.5f * xv[i][j] + 0.5f * q * v1_s[col];
            }
            ((float4*)out)[(size_t)gr * 32 + (cA >> 2)] = *(float4*)&o[0];
            ((float4*)out)[(size_t)gr * 32 + (cB >> 2)] = *(float4*)&o[4];
        }
    }
}

// ---------------------------------------------------------------- launch
extern "C" void kernel_launch(void* const* d_in, const int* in_sizes, int n_in,
                              void* d_out, int out_size) {
    const float* x       = (const float*)d_in[0];
    const void*  ei      = d_in[1];
    const float* ew      = (const float*)d_in[2];
    const float* w_gcn   = (const float*)d_in[3];
    const float* b_gcn   = (const float*)d_in[4];
    const float* w_score = (const float*)d_in[5];
    const float* b_score = (const float*)d_in[6];
    const float* alpha   = (const float*)d_in[7];
    const float* beta    = (const float*)d_in[8];
    const float* w_e1    = (const float*)d_in[9];
    const float* b_e1    = (const float*)d_in[10];
    const float* w_e2    = (const float*)d_in[11];
    const float* b_e2    = (const float*)d_in[12];
    float* out = (float*)d_out;

    int N = in_sizes[0] / D;
    int E = in_sizes[2];
    int nChunks = (N + 127) / 128;
    int NB = (N + 255) / 256;
    int EB = (E + 255) / 256;
    int ZB = ((N > D * D ? N : D * D) + 255) / 256;
    int PB = (N * 32 + 255) / 256;

    const int SMG = 128 * PAD * 4;
    const int SMF = (3 * 128 * PAD + 256) * 4;
    const int SMS = D * D * 4;
    const int SME = (D * PADE + 3 * 128) * 4;

    static int init_done = 0;
    static cudaStream_t s1;
    static cudaEvent_t evFork, evJoin;
    if (!init_done) {
        cudaFuncSetAttribute(k_G,       cudaFuncAttributeMaxDynamicSharedMemorySize, SMG);
        cudaFuncSetAttribute(k_sq,      cudaFuncAttributeMaxDynamicSharedMemorySize, SMS);
        cudaFuncSetAttribute(k_extract, cudaFuncAttributeMaxDynamicSharedMemorySize, SME);
        cudaFuncSetAttribute(k_final,   cudaFuncAttributeMaxDynamicSharedMemorySize, SMF);
        cudaStreamCreateWithFlags(&s1, cudaStreamNonBlocking);
        cudaEventCreateWithFlags(&evFork, cudaEventDisableTiming);
        cudaEventCreateWithFlags(&evJoin, cudaEventDisableTiming);
        init_done = 1;
    }

    // prologue (stream 0)
    k_zero<<<ZB, 256>>>(N);
    k_detect<<<4, 256>>>((const long long*)ei, E, N);
    k_setup<<<1, 128>>>(w_gcn, b_gcn, w_score, b_score);

    // fork: edge chain on s1, Gram+eigen chain on stream 0
    cudaEventRecord(evFork, 0);
    cudaStreamWaitEvent(s1, evFork, 0);

    k_deg<<<EB, 256, 0, s1>>>(ei, E);
    k_p<<<PB, 256, 0, s1>>>(x, N);
    k_dinv<<<NB, 256, 0, s1>>>(N);
    k_edge<<<EB, 256, 0, s1>>>(ei, E);
    k_scores<<<NB, 256, 0, s1>>>(N);
    k_gate<<<EB, 256, 0, s1>>>(ei, ew, alpha, beta, out + (size_t)N * D, E);
    cudaEventRecord(evJoin, s1);

    k_G<<<148, 512, SMG>>>(x, N, nChunks);
    k_gmax<<<1, 256>>>();
    for (int it = 0; it < 12; it++)
        k_sq<<<8, 256, SMS>>>(it);
    k_extract<<<1, 128, SME>>>(w_e1);

    // join
    cudaStreamWaitEvent(0, evJoin, 0);
    k_final<<<148, 512, SMF>>>(x, b_e1, b_e2, w_e1, w_e2, out, N, nChunks);
}

// round 3
// speedup vs baseline: 1.3477x; 1.0825x over previous
#include <cuda_runtime.h>
#include <math.h>

#define D 128
#define PAD 132            // smem row pitch (floats)
#define PADE 129
#define NMAX 65536
#define NSQ 10             // squarings: exponent (NSQ 2^) * (1+NREF)
#define NREF 5

static __device__ int   g_degi[NMAX];
static __device__ float g_dinv[NMAX];
static __device__ float g_p[NMAX];
static __device__ float g_sacc[NMAX];
static __device__ float g_scores[NMAX];
static __device__ __align__(16) float g_G[D * D];
static __device__ __align__(16) float g_Ea[D * D];
static __device__ __align__(16) float g_Eb[D * D];
static __device__ float g_scale[16];
static __device__ float g_v1[D];
static __device__ float g_a1[D];
static __device__ float g_wv[D];
static __device__ float g_bg;
static __device__ int   g_i32;   // 1 => edge_index is int32, 0 => int64

// ---------------------------------------------------------------- utilities
__device__ __forceinline__ void load_edge(const void* ei, int E, int e, int& s, int& t) {
    if (g_i32) {
        const int* p = (const int*)ei;
        s = p[e]; t = p[E + e];
    } else {
        const long long* p = (const long long*)ei;
        s = (int)p[e]; t = (int)p[E + e];
    }
}

__device__ __forceinline__ float sigmoidf_(float z) {
    return 1.0f / (1.0f + expf(-z));
}

__device__ __forceinline__ unsigned smem_u32(const void* p) {
    return (unsigned)__cvta_generic_to_shared(p);
}
__device__ __forceinline__ void cp16(unsigned s, const void* g) {
    asm volatile("cp.async.cg.shared.global [%0], [%1], 16;\n" :: "r"(s), "l"(g));
}
#define CP_COMMIT() asm volatile("cp.async.commit_group;\n" ::)
#define CP_WAIT(n)  asm volatile("cp.async.wait_group %0;\n" :: "n"(n))

// ---------------------------------------------------------------- fused prologue
// blocks [0,ZB): zero; block ZB: dtype detect; block ZB+1: wv/bg setup
__global__ void k_pre(const long long* ei, int E, int N,
                      const float* __restrict__ wg, const float* __restrict__ bgc,
                      const float* __restrict__ ws, const float* __restrict__ bs, int ZB) {
    int b = blockIdx.x, t = threadIdx.x;
    if (b < ZB) {
        int i = b * 256 + t;
        if (i < N) g_degi[i] = 0;
        if (i < D * D) g_G[i] = 0.0f;
        if (i < 16) g_scale[i] = 0.0f;
    } else if (b == ZB) {
        __shared__ int flag;
        if (t == 0) flag = 0;
        __syncthreads();
        int n = E < 1024 ? E : 1024;
        for (int e = t; e < n; e += 256)
            if ((unsigned long long)ei[e] >= (unsigned long long)N) flag = 1;
        __syncthreads();
        if (t == 0) g_i32 = flag;
    } else {
        __shared__ float wss[D];
        if (t < D) wss[t] = ws[t];
        __syncthreads();
        if (t < D) {
            float s = 0.0f;
            #pragma unroll 8
            for (int m = 0; m < D; m++) s += wg[t * D + m] * wss[m];
            g_wv[t] = s;
        }
        if (t == 0) {
            float bsum = bs[0];
            for (int m = 0; m < D; m++) bsum += bgc[m] * wss[m];
            g_bg = bsum;
        }
    }
}

// ---------------------------------------------------------------- edge/score chain (stream s1)
__global__ void k_p(const float* __restrict__ x, int N) {
    int w = (blockIdx.x * blockDim.x + threadIdx.x) >> 5;
    int lane = threadIdx.x & 31;
    if (w >= N) return;
    float4 xv = ((const float4*)x)[(size_t)w * 32 + lane];
    float4 wv = *(const float4*)&g_wv[lane * 4];
    float s = xv.x * wv.x + xv.y * wv.y + xv.z * wv.z + xv.w * wv.w;
    #pragma unroll
    for (int o = 16; o; o >>= 1) s += __shfl_xor_sync(0xffffffffu, s, o);
    if (lane == 0) g_p[w] = s;
}

__global__ void k_deg(const void* ei, int E) {
    int e = blockIdx.x * 256 + threadIdx.x;
    if (e >= E) return;
    int t = g_i32 ? ((const int*)ei)[E + e] : (int)((const long long*)ei)[E + e];
    atomicAdd(&g_degi[t], 1);
}

__global__ void k_dinv(int N) {
    int i = blockIdx.x * 256 + threadIdx.x;
    if (i >= N) return;
    float di = rsqrtf((float)(g_degi[i] + 1));   // +1 = self loop
    g_dinv[i] = di;
    g_sacc[i] = di * di * g_p[i];
}

__global__ void k_edge(const void* ei, int E) {
    int e = blockIdx.x * 256 + threadIdx.x;
    if (e >= E) return;
    int s, t; load_edge(ei, E, e, s, t);
    atomicAdd(&g_sacc[t], g_dinv[s] * g_dinv[t] * g_p[s]);
}

__global__ void k_scores(int N) {
    int i = blockIdx.x * 256 + threadIdx.x;
    if (i >= N) return;
    g_scores[i] = sigmoidf_(g_sacc[i] + g_bg);
}

__global__ void k_gate(const void* ei, const float* __restrict__ ew,
                       const float* __restrict__ al, const float* __restrict__ be,
                       float* __restrict__ out, int E) {
    int e = blockIdx.x * 256 + threadIdx.x;
    if (e >= E) return;
    int s, t; load_edge(ei, E, e, s, t);
    float z = al[0] * (g_scores[s] + g_scores[t]) + be[0];
    out[e] = ew[e] * sigmoidf_(z);
}

// ---------------------------------------------------------------- Gram, cp.async double-buffered
__global__ __launch_bounds__(512, 1) void k_G(const float* __restrict__ x, int N, int nChunks) {
    extern __shared__ float sm[];
    float* bufs[2] = { sm, sm + 128 * PAD };
    int tid = threadIdx.x;
    int ty = tid >> 4, tx = tid & 15;
    int r0 = ty * 4, cA = tx * 4, cB = cA + 64;
    int stride = gridDim.x;

    float acc[4][8];
    #pragma unroll
    for (int i = 0; i < 4; i++)
        #pragma unroll
        for (int j = 0; j < 8; j++) acc[i][j] = 0.0f;

    int ch = blockIdx.x;
    // prefetch first chunk
    if (ch < nChunks) {
        int R0 = ch * 128;
        if (R0 + 128 <= N) {
            #pragma unroll
            for (int u = 0; u < 8; u++) {
                int idx = tid + u * 512;
                int r = idx >> 5, c4 = idx & 31;
                cp16(smem_u32(&bufs[0][r * PAD + c4 * 4]), &x[((size_t)(R0 + r)) * 128 + c4 * 4]);
            }
        } else {
            #pragma unroll
            for (int u = 0; u < 8; u++) {
                int idx = tid + u * 512;
                int r = idx >> 5, c4 = idx & 31;
                int gr = R0 + r;
                float4 v = (gr < N) ? ((const float4*)x)[(size_t)gr * 32 + c4]
                                    : make_float4(0.f, 0.f, 0.f, 0.f);
                *(float4*)&bufs[0][r * PAD + c4 * 4] = v;
            }
        }
        CP_COMMIT();
    }

    int cur = 0;
    for (; ch < nChunks; ch += stride) {
        int nxt = ch + stride;
        if (nxt < nChunks) {
            float* bn = bufs[cur ^ 1];
            int R0 = nxt * 128;
            if (R0 + 128 <= N) {
                #pragma unroll
                for (int u = 0; u < 8; u++) {
                    int idx = tid + u * 512;
                    int r = idx >> 5, c4 = idx & 31;
                    cp16(smem_u32(&bn[r * PAD + c4 * 4]), &x[((size_t)(R0 + r)) * 128 + c4 * 4]);
                }
            } else {
                #pragma unroll
                for (int u = 0; u < 8; u++) {
                    int idx = tid + u * 512;
                    int r = idx >> 5, c4 = idx & 31;
                    int gr = R0 + r;
                    float4 v = (gr < N) ? ((const float4*)x)[(size_t)gr * 32 + c4]
                                        : make_float4(0.f, 0.f, 0.f, 0.f);
                    *(float4*)&bn[r * PAD + c4 * 4] = v;
                }
            }
            CP_COMMIT();
            CP_WAIT(1);
        } else {
            CP_WAIT(0);
        }
        __syncthreads();
        const float* bc = bufs[cur];
        #pragma unroll 4
        for (int k = 0; k < 128; k++) {
            float4 av = *(const float4*)&bc[k * PAD + r0];
            float4 b0 = *(const float4*)&bc[k * PAD + cA];
            float4 b1 = *(const float4*)&bc[k * PAD + cB];
            float a[4] = {av.x, av.y, av.z, av.w};
            float b[8] = {b0.x, b0.y, b0.z, b0.w, b1.x, b1.y, b1.z, b1.w};
            #pragma unroll
            for (int i = 0; i < 4; i++)
                #pragma unroll
                for (int j = 0; j < 8; j++) acc[i][j] += a[i] * b[j];
        }
        cur ^= 1;
        __syncthreads();
    }
    #pragma unroll
    for (int i = 0; i < 4; i++)
        #pragma unroll
        for (int j = 0; j < 4; j++) {
            atomicAdd(&g_G[(r0 + i) * D + cA + j], acc[i][j]);
            atomicAdd(&g_G[(r0 + i) * D + cB + j], acc[i][j + 4]);
        }
}

// ---------------------------------------------------------------- matrix squaring
// it==0 computes the normalization max inline (redundantly per block).
__global__ void k_sq(int it) {
    extern __shared__ float As[];   // 128*128
    const float* in = (it == 0) ? g_G : ((it & 1) ? g_Ea : g_Eb);
    float* outp = (it & 1) ? g_Eb : g_Ea;
    int tid = threadIdx.x;
    __shared__ float redm[8];

    if (it == 0) {
        float m = 0.0f;
        for (int idx = tid; idx < D * D / 4; idx += 256) {
            float4 v = ((const float4*)in)[idx];
            ((float4*)As)[idx] = v;
            m = fmaxf(m, fmaxf(fmaxf(fabsf(v.x), fabsf(v.y)), fmaxf(fabsf(v.z), fabsf(v.w))));
        }
        #pragma unroll
        for (int o = 16; o; o >>= 1) m = fmaxf(m, __shfl_xor_sync(0xffffffffu, m, o));
        if ((tid & 31) == 0) redm[tid >> 5] = m;
        __syncthreads();
        if (tid < 32) {
            float mm = (tid < 8) ? redm[tid] : 0.0f;
            #pragma unroll
            for (int o = 4; o; o >>= 1) mm = fmaxf(mm, __shfl_xor_sync(0xffffffffu, mm, o));
            if (tid == 0) redm[0] = mm;
        }
        __syncthreads();
        float inv = 1.0f / redm[0];
        for (int idx = tid; idx < D * D / 4; idx += 256) {
            float4 v = ((float4*)As)[idx];
            v.x *= inv; v.y *= inv; v.z *= inv; v.w *= inv;
            ((float4*)As)[idx] = v;
        }
    } else {
        float inv = 1.0f / g_scale[it];
        for (int idx = tid; idx < D * D / 4; idx += 256) {
            float4 v = ((const float4*)in)[idx];
            v.x *= inv; v.y *= inv; v.z *= inv; v.w *= inv;
            ((float4*)As)[idx] = v;
        }
    }
    __syncthreads();

    int ty = tid >> 5, tx = tid & 31;
    int r0 = blockIdx.x * 16 + ty * 2, c0 = tx * 4;
    float acc0[4] = {0.f, 0.f, 0.f, 0.f};
    float acc1[4] = {0.f, 0.f, 0.f, 0.f};
    #pragma unroll 4
    for (int k = 0; k < D; k++) {
        float a0 = As[r0 * D + k];
        float a1v = As[(r0 + 1) * D + k];
        float4 b = *(const float4*)&As[k * D + c0];
        acc0[0] += a0 * b.x; acc0[1] += a0 * b.y; acc0[2] += a0 * b.z; acc0[3] += a0 * b.w;
        acc1[0] += a1v * b.x; acc1[1] += a1v * b.y; acc1[2] += a1v * b.z; acc1[3] += a1v * b.w;
    }
    *(float4*)&outp[r0 * D + c0] = *(float4*)&acc0[0];
    *(float4*)&outp[(r0 + 1) * D + c0] = *(float4*)&acc1[0];
    float m = 0.0f;
    #pragma unroll
    for (int j = 0; j < 4; j++) m = fmaxf(m, fmaxf(fabsf(acc0[j]), fabsf(acc1[j])));
    #pragma unroll
    for (int o = 16; o; o >>= 1) m = fmaxf(m, __shfl_xor_sync(0xffffffffu, m, o));
    if (tx == 0) atomicMax((int*)&g_scale[it + 1], __float_as_int(m));  // values >= 0
}

// ---------------------------------------------------------------- v1 extraction + a1
__global__ void k_extract(const float* __restrict__ w1) {
    extern __shared__ float sm[];
    float* As = sm;                  // 128*PADE
    float* vv = sm + D * PADE;
    float* uu = vv + D;
    float* red = uu + D;
    __shared__ int redi[128];
    __shared__ int jm;
    int t = threadIdx.x;             // 128 threads

    for (int idx = t; idx < D * D; idx += 128) {
        int r = idx >> 7, c = idx & 127;
        As[r * PADE + c] = g_Eb[idx];
    }
    __syncthreads();
    red[t] = As[t * PADE + t]; redi[t] = t;
    __syncthreads();
    for (int s = 64; s > 0; s >>= 1) {
        if (t < s && red[t + s] > red[t]) { red[t] = red[t + s]; redi[t] = redi[t + s]; }
        __syncthreads();
    }
    if (t == 0) jm = redi[0];
    __syncthreads();
    vv[t] = As[jm * PADE + t];
    __syncthreads();

    for (int itr = 0; itr < NREF; itr++) {
        float s = 0.0f;
        #pragma unroll 8
        for (int c = 0; c < D; c++) s += As[t * PADE + c] * vv[c];
        uu[t] = s;
        red[t] = s * s;
        __syncthreads();
        for (int r2 = 64; r2 > 0; r2 >>= 1) {
            if (t < r2) red[t] += red[t + r2];
            __syncthreads();
        }
        float inv = rsqrtf(fmaxf(red[0], 1e-30f));
        __syncthreads();
        vv[t] = uu[t] * inv;
        __syncthreads();
    }

    g_v1[t] = vv[t];
    float a = 0.0f;
    #pragma unroll 8
    for (int d2 = 0; d2 < D; d2++) a += vv[d2] * w1[d2 * D + t];
    g_a1[t] = a;
}

// ---------------------------------------------------------------- fused enhancer, reg-prefetch pipelined
// out = (relu(0.5 x@W1 + 0.5 q a1^T + b1) @ W2 + b2)*scores + 0.5 x + 0.5 q v1^T
__global__ __launch_bounds__(512, 1) void k_final(const float* __restrict__ x,
                        const float* __restrict__ b1, const float* __restrict__ b2,
                        const float* __restrict__ w1, const float* __restrict__ w2,
                        float* __restrict__ out, int N, int nChunks) {
    extern __shared__ float sm[];
    float* xs  = sm;                       // x chunk, later relu(z)
    float* w1s = sm + 128 * PAD;
    float* w2s = w1s + 128 * PAD;
    float* q_s = w2s + 128 * PAD;
    float* sc_s = q_s + 128;
    __shared__ float v1_s[D], a1_s[D], be1_s[D], be2_s[D];

    int tid = threadIdx.x;
    int ty = tid >> 4, tx = tid & 15;
    int r0 = ty * 4, cA = tx * 4, cB = cA + 64;
    int stride = gridDim.x;

    for (int idx = tid; idx < D * 32; idx += 512) {
        int r = idx >> 5, c4 = idx & 31;
        *(float4*)&w1s[r * PAD + c4 * 4] = ((const float4*)w1)[idx];
        *(float4*)&w2s[r * PAD + c4 * 4] = ((const float4*)w2)[idx];
    }
    if (tid < D) {
        v1_s[tid] = g_v1[tid]; a1_s[tid] = g_a1[tid];
        be1_s[tid] = b1[tid];  be2_s[tid] = b2[tid];
    }

    float4 pf[8];
    int ch = blockIdx.x;
    if (ch < nChunks) {
        int R0 = ch * 128;
        #pragma unroll
        for (int u = 0; u < 8; u++) {
            int idx = tid + u * 512;
            int r = idx >> 5, c4 = idx & 31;
            int gr = R0 + r;
            pf[u] = (gr < N) ? ((const float4*)x)[(size_t)gr * 32 + c4]
                             : make_float4(0.f, 0.f, 0.f, 0.f);
        }
    }

    for (; ch < nChunks; ch += stride) {
        int R0 = ch * 128;
        __syncthreads();                  // xs free of previous-iteration reads
        #pragma unroll
        for (int u = 0; u < 8; u++) {
            int idx = tid + u * 512;
            int r = idx >> 5, c4 = idx & 31;
            *(float4*)&xs[r * PAD + c4 * 4] = pf[u];
        }
        if (tid < 128) sc_s[tid] = (R0 + tid < N) ? g_scores[R0 + tid] : 0.0f;
        __syncthreads();
        if (tid < 128) {
            float q = 0.0f;
            #pragma unroll 8
            for (int d = 0; d < D; d++) q += xs[tid * PAD + d] * v1_s[d];
            q_s[tid] = q;
        }
        // prefetch next chunk into registers; LDGs overlap both GEMMs below
        int nxt = ch + stride;
        if (nxt < nChunks) {
            int R1 = nxt * 128;
            #pragma unroll
            for (int u = 0; u < 8; u++) {
                int idx = tid + u * 512;
                int r = idx >> 5, c4 = idx & 31;
                int gr = R1 + r;
                pf[u] = (gr < N) ? ((const float4*)x)[(size_t)gr * 32 + c4]
                                 : make_float4(0.f, 0.f, 0.f, 0.f);
            }
        }
        __syncthreads();   // q_s visible

        // GEMM1: z = x @ W1
        float acc[4][8];
        #pragma unroll
        for (int i = 0; i < 4; i++)
            #pragma unroll
            for (int j = 0; j < 8; j++) acc[i][j] = 0.0f;
        #pragma unroll 4
        for (int k = 0; k < 128; k++) {
            float a[4];
            #pragma unroll
            for (int i = 0; i < 4; i++) a[i] = xs[(r0 + i) * PAD + k];
            float4 b0 = *(const float4*)&w1s[k * PAD + cA];
            float4 b1v = *(const float4*)&w1s[k * PAD + cB];
            float b[8] = {b0.x, b0.y, b0.z, b0.w, b1v.x, b1v.y, b1v.z, b1v.w};
            #pragma unroll
            for (int i = 0; i < 4; i++)
                #pragma unroll
                for (int j = 0; j < 8; j++) acc[i][j] += a[i] * b[j];
        }
        #pragma unroll
        for (int i = 0; i < 4; i++) {
            float q = q_s[r0 + i];
            #pragma unroll
            for (int j = 0; j < 8; j++) {
                int col = (j < 4) ? (cA + j) : (cB + j - 4);
                float z = 0.5f * acc[i][j] + 0.5f * q * a1_s[col] + be1_s[col];
                acc[i][j] = z > 0.0f ? z : 0.0f;
            }
        }
        __syncthreads();
        #pragma unroll
        for (int i = 0; i < 4; i++) {
            *(float4*)&xs[(r0 + i) * PAD + cA] = *(float4*)&acc[i][0];
            *(float4*)&xs[(r0 + i) * PAD + cB] = *(float4*)&acc[i][4];
        }
        __syncthreads();

        // GEMM2: enh = relu(z) @ W2
        #pragma unroll
        for (int i = 0; i < 4; i++)
            #pragma unroll
            for (int j = 0; j < 8; j++) acc[i][j] = 0.0f;
        #pragma unroll 4
        for (int k = 0; k < 128; k++) {
            float a[4];
            #pragma unroll
            for (int i = 0; i < 4; i++) a[i] = xs[(r0 + i) * PAD + k];
            float4 b0 = *(const float4*)&w2s[k * PAD + cA];
            float4 b1v = *(const float4*)&w2s[k * PAD + cB];
            float b[8] = {b0.x, b0.y, b0.z, b0.w, b1v.x, b1v.y, b1v.z, b1v.w};
            #pragma unroll
            for (int i = 0; i < 4; i++)
                #pragma unroll
                for (int j = 0; j < 8; j++) acc[i][j] += a[i] * b[j];
        }
        // epilogue: residual (x re-read hits L2) + write
        #pragma unroll
        for (int i = 0; i < 4; i++) {
            int gr = R0 + r0 + i;
            if (gr >= N) continue;
            float sc = sc_s[r0 + i], q = q_s[r0 + i];
            float4 xa = ((const float4*)x)[(size_t)gr * 32 + (cA >> 2)];
            float4 xb = ((const float4*)x)[(size_t)gr * 32 + (cB >> 2)];
            float xv[8] = {xa.x, xa.y, xa.z, xa.w, xb.x, xb.y, xb.z, xb.w};
            float o[8];
            #pragma unroll
            for (int j = 0; j < 8; j++) {
                int col = (j < 4) ? (cA + j) : (cB + j - 4);
                o[j] = (acc[i][j] + be2_s[col]) * sc
                     + 0.5f * xv[j] + 0.5f * q * v1_s[col];
            }
            ((float4*)out)[(size_t)gr * 32 + (cA >> 2)] = *(float4*)&o[0];
            ((float4*)out)[(size_t)gr * 32 + (cB >> 2)] = *(float4*)&o[4];
        }
    }
}

// ---------------------------------------------------------------- launch
extern "C" void kernel_launch(void* const* d_in, const int* in_sizes, int n_in,
                              void* d_out, int out_size) {
    const float* x       = (const float*)d_in[0];
    const void*  ei      = d_in[1];
    const float* ew      = (const float*)d_in[2];
    const float* w_gcn   = (const float*)d_in[3];
    const float* b_gcn   = (const float*)d_in[4];
    const float* w_score = (const float*)d_in[5];
    const float* b_score = (const float*)d_in[6];
    const float* alpha   = (const float*)d_in[7];
    const float* beta    = (const float*)d_in[8];
    const float* w_e1    = (const float*)d_in[9];
    const float* b_e1    = (const float*)d_in[10];
    const float* w_e2    = (const float*)d_in[11];
    const float* b_e2    = (const float*)d_in[12];
    float* out = (float*)d_out;

    int N = in_sizes[0] / D;
    int E = in_sizes[2];
    int nChunks = (N + 127) / 128;
    int NB = (N + 255) / 256;
    int EB = (E + 255) / 256;
    int ZB = ((N > D * D ? N : D * D) + 255) / 256;
    int PB = (N * 32 + 255) / 256;

    const int SMG = 2 * 128 * PAD * 4;
    const int SMF = (3 * 128 * PAD + 256) * 4;
    const int SMS = D * D * 4;
    const int SME = (D * PADE + 3 * 128) * 4;

    static int init_done = 0;
    static cudaStream_t s1;
    static cudaEvent_t evFork, evJoin;
    if (!init_done) {
        cudaFuncSetAttribute(k_G,       cudaFuncAttributeMaxDynamicSharedMemorySize, SMG);
        cudaFuncSetAttribute(k_sq,      cudaFuncAttributeMaxDynamicSharedMemorySize, SMS);
        cudaFuncSetAttribute(k_extract, cudaFuncAttributeMaxDynamicSharedMemorySize, SME);
        cudaFuncSetAttribute(k_final,   cudaFuncAttributeMaxDynamicSharedMemorySize, SMF);
        cudaStreamCreateWithFlags(&s1, cudaStreamNonBlocking);
        cudaEventCreateWithFlags(&evFork, cudaEventDisableTiming);
        cudaEventCreateWithFlags(&evJoin, cudaEventDisableTiming);
        init_done = 1;
    }

    // fused prologue
    k_pre<<<ZB + 2, 256>>>((const long long*)ei, E, N, w_gcn, b_gcn, w_score, b_score, ZB);

    // fork: edge chain on s1, Gram+eigen on stream 0
    cudaEventRecord(evFork, 0);
    cudaStreamWaitEvent(s1, evFork, 0);

    k_deg<<<EB, 256, 0, s1>>>(ei, E);
    k_p<<<PB, 256, 0, s1>>>(x, N);
    k_dinv<<<NB, 256, 0, s1>>>(N);
    k_edge<<<EB, 256, 0, s1>>>(ei, E);
    k_scores<<<NB, 256, 0, s1>>>(N);
    k_gate<<<EB, 256, 0, s1>>>(ei, ew, alpha, beta, out + (size_t)N * D, E);
    cudaEventRecord(evJoin, s1);

    k_G<<<148, 512, SMG>>>(x, N, nChunks);
    for (int it = 0; it < NSQ; it++)
        k_sq<<<8, 256, SMS>>>(it);
    k_extract<<<1, 128, SME>>>(w_e1);

    cudaStreamWaitEvent(0, evJoin, 0);
    k_final<<<148, 512, SMF>>>(x, b_e1, b_e2, w_e1, w_e2, out, N, nChunks);
}